// round 14
// baseline (speedup 1.0000x reference)
#include <cuda_runtime.h>
#include <cuda_fp16.h>
#include <math.h>

// Problem constants (fixed by the dataset)
#define Bsz 1024
#define Tn  200
#define LXn 190
#define LYn 50
#define Hd  256
#define XDd 64
#define YDd 64

#define GRID 128
#define NTHR 512
#define ROWS 8

// row strides (in halves) for fp16 activation buffers
#define STW 264    // 256-wide buffers  (264*2B = 132 words, %32 = 4 -> staggered)
#define STA 600    // 576-wide buffers  (600*2B = 300 words, %32 = 12 -> staggered)

// ---------------- device scratch ---------------------------------------------
__device__ float g_dt[Tn];
__device__ int   g_obs[Tn];
__device__ int   g_qm [Tn];
// saved new_y at query steps, fp16 row-major per CTA: [q][cta][row(8)][col(256)]
__device__ __align__(16) __half g_ybh[(size_t)LYn*GRID*ROWS*Hd];

// fp16 TRANSPOSED weights [n][k] (k contiguous), converted once by conv_kernel
__device__ __align__(16) __half c_fw1t [256*256];
__device__ __align__(16) __half c_fw2t [256*256];
__device__ __align__(16) __half c_ugw1t[256*576];
__device__ __align__(16) __half c_ugw2t[256*256];
__device__ __align__(16) __half c_rgw1t[256*576];
__device__ __align__(16) __half c_rgw2t[256*256];
__device__ __align__(16) __half c_nsw1t[256*576];
__device__ __align__(16) __half c_nsw2t[512*256];
__device__ __align__(16) __half c_ow1t [256*256];
__device__ __align__(16) __half c_ow2t [64*256];

// ---------------- helpers -----------------------------------------------------
__device__ __forceinline__ float sigm(float x) {
    return __fdividef(1.0f, 1.0f + __expf(-x));
}
__device__ __forceinline__ float tanh_f(float x) {
    return fmaf(2.0f, sigm(2.0f*x), -1.0f);   // |err| ~1e-6 << budget
}

// m16n8k16 f16 MMA, fp32 accumulate. Rows 8-15 of A are zero (a1 = a3 = 0),
// so only c[0], c[1] (row g = lane>>2, cols 2t, 2t+1) are meaningful.
__device__ __forceinline__ void mma16(float* c, unsigned a0, unsigned a2,
                                      unsigned b0, unsigned b1) {
    asm volatile(
        "mma.sync.aligned.m16n8k16.row.col.f32.f16.f16.f32 "
        "{%0,%1,%2,%3}, {%4,%5,%6,%7}, {%8,%9}, {%0,%1,%2,%3};"
        : "+f"(c[0]), "+f"(c[1]), "+f"(c[2]), "+f"(c[3])
        : "r"(a0), "r"(0u), "r"(a2), "r"(0u), "r"(b0), "r"(b1));
}

// One warp computes NT n-tiles (8 cols each) over full K with in-register acc.
// A: smem fp16 [8 rows][strideA halves]; Wt: global fp16 [n][ldk halves].
template<int K, int NT>
__device__ __forceinline__ void hgemm(const __half* A, int strideA,
                                      const __half* __restrict__ Wt, int ldk,
                                      int nbase, int g, int t, float* acc)
{
#pragma unroll
    for (int i = 0; i < NT*4; i++) acc[i] = 0.0f;
    const __half* arow = A + g*strideA + 2*t;
#pragma unroll 2
    for (int k0 = 0; k0 < K; k0 += 16) {
        unsigned a0 = *(const unsigned*)(arow + k0);
        unsigned a2 = *(const unsigned*)(arow + k0 + 8);
#pragma unroll
        for (int tl = 0; tl < NT; tl++) {
            const __half* wp = Wt + (size_t)(nbase + tl*8 + g)*ldk + k0 + 2*t;
            unsigned b0 = __ldg((const unsigned*)wp);
            unsigned b1 = __ldg((const unsigned*)(wp + 8));
            mma16(acc + 4*tl, a0, a2, b0, b1);
        }
    }
}

// ---------------- init: dt / obs-slot / query maps ---------------------------
__global__ void init_kernel(const float* __restrict__ x_time,
                            const int* __restrict__ x_idx,
                            const int* __restrict__ y_idx) {
    int tid = threadIdx.x;
    for (int t = tid; t < Tn; t += blockDim.x) { g_obs[t] = -1; g_qm[t] = -1; }
    __syncthreads();
    for (int i = tid; i < LXn; i += blockDim.x) g_obs[x_idx[i]] = i;
    for (int j = tid; j < LYn; j += blockDim.x) g_qm[y_idx[j]] = j;
    __syncthreads();
    for (int t = tid; t < Tn; t += blockDim.x) {
        float d;
        float tlast = x_time[Tn - 1];
        if (t == 0)      d = tlast - (tlast + 0.01f);
        else if (t == 1) d = tlast - x_time[0];
        else             d = x_time[t - 2] - x_time[t - 1];
        g_dt[t] = d;
    }
}

// ---------------- conv: fp32 [k][n] -> fp16 transposed [n][k] -----------------
__device__ void convT(__half* dst, const float* __restrict__ src, int K, int N,
                      int g0, int gs) {
    for (int idx = g0; idx < N*K; idx += gs) {
        int n = idx / K, k = idx - n*K;
        dst[idx] = __float2half_rn(src[(size_t)k*N + n]);
    }
}
__global__ void conv_kernel(const float* fw1, const float* fw2,
                            const float* ugw1, const float* ugw2,
                            const float* rgw1, const float* rgw2,
                            const float* nsw1, const float* nsw2,
                            const float* ow1, const float* ow2) {
    int g0 = blockIdx.x*blockDim.x + threadIdx.x;
    int gs = gridDim.x*blockDim.x;
    convT(c_fw1t,  fw1,  256, 256, g0, gs);
    convT(c_fw2t,  fw2,  256, 256, g0, gs);
    convT(c_ugw1t, ugw1, 576, 256, g0, gs);
    convT(c_ugw2t, ugw2, 256, 256, g0, gs);
    convT(c_rgw1t, rgw1, 576, 256, g0, gs);
    convT(c_rgw2t, rgw2, 256, 256, g0, gs);
    convT(c_nsw1t, nsw1, 576, 256, g0, gs);
    convT(c_nsw2t, nsw2, 256, 512, g0, gs);
    convT(c_ow1t,  ow1,  256, 256, g0, gs);
    convT(c_ow2t,  ow2,  256, 64,  g0, gs);
}

// ---------------- smem layout --------------------------------------------------
// halves:
//   hA  [8][600]  cat(hi, s, x)        hC  [8][600]  cat(c1, c2, x)
//   hH, hTF, hTU, hTR, hTN, hYB : [8][264]
// floats (exact side-state for epilogue math):
//   sHf, sSf, sHIf, sUf : [8][256]
#define SMEM_BYTES (2*(2*4800) + 2*(6*2112) + 4*8192)   // 77312

// ---------------- persistent per-CTA recurrence (HMMA) -------------------------
__global__ void __launch_bounds__(NTHR, 1)
recur_kernel(const float* __restrict__ xd, const float* __restrict__ xm,
             const float* __restrict__ ug_b1, const float* __restrict__ ug_b2,
             const float* __restrict__ rg_b1, const float* __restrict__ rg_b2,
             const float* __restrict__ ns_b1, const float* __restrict__ ns_b2,
             const float* __restrict__ out_b1, const float* __restrict__ out_b2,
             const float* __restrict__ f_b1, const float* __restrict__ f_b2,
             float* __restrict__ out)
{
    extern __shared__ __align__(16) char smraw[];
    __half* hA  = (__half*)smraw;            // 4800
    __half* hC  = hA  + 4800;                // 4800
    __half* hH  = hC  + 4800;                // 2112 each below
    __half* hTF = hH  + 2112;
    __half* hTU = hTF + 2112;
    __half* hTR = hTU + 2112;
    __half* hTN = hTR + 2112;
    __half* hYB = hTN + 2112;
    float*  sHf  = (float*)(hYB + 2112);     // 2048 each
    float*  sSf  = sHf  + 2048;
    float*  sHIf = sSf  + 2048;
    float*  sUf  = sHIf + 2048;

    const int tid  = threadIdx.x;
    const int wid  = tid >> 5;
    const int lane = tid & 31;
    const int g    = lane >> 2;   // row 0..7 / B-col group
    const int t4   = lane & 3;    // k-subgroup / D col pair
    const int cta  = blockIdx.x;
    const int m0   = cta * ROWS;

    // zero initial state: h (fp16 + fp32), s (fp16 in hA[256:512] + fp32)
    for (int i = tid; i < 2048; i += NTHR) {
        sHf[i] = 0.0f; sSf[i] = 0.0f;
        int r = i >> 8, c = i & 255;
        hH[r*STW + c] = __float2half(0.0f);
        hA[r*STA + 256 + c] = __float2half(0.0f);
    }
    __syncthreads();

    float acc[16];

    for (int tstep = 0; tstep < Tn; tstep++) {
        const int   obs = g_obs[tstep];
        const int   q   = g_qm[tstep];
        const float dt  = g_dt[tstep];

        // ---- prologue: x -> hA/hC[512:576] (fp16) ----
        if (tid < XDd) {
            for (int r = 0; r < 8; r++) {
                float xv = 0.0f;
                if (obs >= 0) {
                    int off = ((m0 + r)*LXn + obs)*XDd + tid;
                    xv = __ldg(xd + off) * __ldg(xm + off);
                }
                __half h = __float2half_rn(xv);
                hA[r*STA + 512 + tid] = h;
                hC[r*STA + 512 + tid] = h;
            }
        }
        // (first consumer is S3/S5 — syncs in between)

        // ---- S1: tf = tanh(h @ f_w1 + b1)  [N=256, 2 tiles/warp] ----
        hgemm<256,2>(hH, STW, c_fw1t, 256, wid*16, g, t4, acc);
        {
#pragma unroll
            for (int tl = 0; tl < 2; tl++) {
                int n = wid*16 + tl*8 + 2*t4;
                float v0 = acc[4*tl]   + __ldg(f_b1 + n);
                float v1 = acc[4*tl+1] + __ldg(f_b1 + n + 1);
                *(__half2*)(hTF + g*STW + n) = __floats2half2_rn(tanh_f(v0), tanh_f(v1));
            }
        }
        __syncthreads();

        // ---- S2: hi = h + dt*(tf @ f_w2 + b2) -> hA[0:256] + sHIf ----
        hgemm<256,2>(hTF, STW, c_fw2t, 256, wid*16, g, t4, acc);
        {
#pragma unroll
            for (int tl = 0; tl < 2; tl++) {
                int n = wid*16 + tl*8 + 2*t4;
                float2 h2 = *(float2*)(sHf + g*256 + n);
                float hi0 = h2.x + dt*(acc[4*tl]   + __ldg(f_b2 + n));
                float hi1 = h2.y + dt*(acc[4*tl+1] + __ldg(f_b2 + n + 1));
                *(__half2*)(hA + g*STA + n) = __floats2half2_rn(hi0, hi1);
                *(float2*)(sHIf + g*256 + n) = make_float2(hi0, hi1);
            }
        }
        __syncthreads();

        // ---- S3: tu / tr = tanh(cat(hi,s,x) @ {ug,rg}_w1 + b)  [K=576] ----
        {
            const bool isr = (wid >= 8);
            int nb = (isr ? (wid - 8) : wid) * 32;
            hgemm<576,4>(hA, STA, isr ? c_rgw1t : c_ugw1t, 576, nb, g, t4, acc);
            const float* bias = isr ? rg_b1 : ug_b1;
            __half* dst = isr ? hTR : hTU;
#pragma unroll
            for (int tl = 0; tl < 4; tl++) {
                int n = nb + tl*8 + 2*t4;
                float v0 = acc[4*tl]   + __ldg(bias + n);
                float v1 = acc[4*tl+1] + __ldg(bias + n + 1);
                *(__half2*)(dst + g*STW + n) = __floats2half2_rn(tanh_f(v0), tanh_f(v1));
            }
        }
        __syncthreads();

        // ---- S4: u = sig(tu@ug_w2+b); r = sig(tr@rg_w2+b); c1=hi*r; c2=s*r ----
        {
            float ar[8];
            hgemm<256,2>(hTU, STW, c_ugw2t, 256, wid*16, g, t4, acc);
            hgemm<256,2>(hTR, STW, c_rgw2t, 256, wid*16, g, t4, ar);
#pragma unroll
            for (int tl = 0; tl < 2; tl++) {
                int n = wid*16 + tl*8 + 2*t4;
                float u0 = sigm(acc[4*tl]   + __ldg(ug_b2 + n));
                float u1 = sigm(acc[4*tl+1] + __ldg(ug_b2 + n + 1));
                float r0 = sigm(ar[4*tl]    + __ldg(rg_b2 + n));
                float r1 = sigm(ar[4*tl+1]  + __ldg(rg_b2 + n + 1));
                float2 hi = *(float2*)(sHIf + g*256 + n);
                float2 ss = *(float2*)(sSf  + g*256 + n);
                *(float2*)(sUf + g*256 + n) = make_float2(u0, u1);
                *(__half2*)(hC + g*STA + n)       = __floats2half2_rn(hi.x*r0, hi.y*r1);
                *(__half2*)(hC + g*STA + 256 + n) = __floats2half2_rn(ss.x*r0, ss.y*r1);
            }
        }
        __syncthreads();

        // ---- S5: tn = tanh(cat(c1,c2,x) @ ns_w1 + b)  [K=576, N=256] ----
        hgemm<576,2>(hC, STA, c_nsw1t, 576, wid*16, g, t4, acc);
        {
#pragma unroll
            for (int tl = 0; tl < 2; tl++) {
                int n = wid*16 + tl*8 + 2*t4;
                float v0 = acc[4*tl]   + __ldg(ns_b1 + n);
                float v1 = acc[4*tl+1] + __ldg(ns_b1 + n + 1);
                *(__half2*)(hTN + g*STW + n) = __floats2half2_rn(tanh_f(v0), tanh_f(v1));
            }
        }
        __syncthreads();

        // ---- S6: ns | std (N=512), gated state update ----
        {
            const bool sd = (wid >= 8);
            int nb = sd ? 256 + (wid - 8)*32 : wid*32;
            hgemm<256,4>(hTN, STW, c_nsw2t, 256, nb, g, t4, acc);
#pragma unroll
            for (int tl = 0; tl < 4; tl++) {
                int n = nb + tl*8 + 2*t4;
                float v0 = acc[4*tl]   + __ldg(ns_b2 + n);
                float v1 = acc[4*tl+1] + __ldg(ns_b2 + n + 1);
                if (!sd) {
                    float2 u  = *(float2*)(sUf  + g*256 + n);
                    float2 hi = *(float2*)(sHIf + g*256 + n);
                    float hy0 = (1.0f - u.x)*v0 + u.x*hi.x;
                    float hy1 = (1.0f - u.y)*v1 + u.y*hi.y;
                    *(float2*)(sHf + g*256 + n) = make_float2(hy0, hy1);
                    __half2 hp = __floats2half2_rn(hy0, hy1);
                    *(__half2*)(hH + g*STW + n) = hp;
                    if (q >= 0)
                        *(__half2*)(g_ybh + (((size_t)q*GRID + cta)*ROWS + g)*Hd + n) = hp;
                } else {
                    int nn = n - 256;
                    float2 u  = *(float2*)(sUf + g*256 + nn);
                    float2 ss = *(float2*)(sSf + g*256 + nn);
                    float sy0 = fabsf((1.0f - u.x)*fabsf(v0) + u.x*ss.x);
                    float sy1 = fabsf((1.0f - u.y)*fabsf(v1) + u.y*ss.y);
                    *(float2*)(sSf + g*256 + nn) = make_float2(sy0, sy1);
                    *(__half2*)(hA + g*STA + 256 + nn) = __floats2half2_rn(sy0, sy1);
                }
            }
        }
        __syncthreads();
    }

    // ---- deferred out-MLP over the 50 saved query states ----
    for (int q = 0; q < LYn; q++) {
        // copy yb (fp16, [8][256] packed) into padded hYB
        {
            const unsigned* src = (const unsigned*)(g_ybh + ((size_t)q*GRID + cta)*ROWS*Hd);
            for (int i = tid; i < 1024; i += NTHR) {
                int r = i >> 7, pr = i & 127;
                *(unsigned*)(hYB + r*STW + pr*2) = src[r*128 + pr];
            }
        }
        __syncthreads();

        // O1: t_o = tanh(yb @ out_w1 + b1)
        hgemm<256,2>(hYB, STW, c_ow1t, 256, wid*16, g, t4, acc);
        {
#pragma unroll
            for (int tl = 0; tl < 2; tl++) {
                int n = wid*16 + tl*8 + 2*t4;
                float v0 = acc[4*tl]   + __ldg(out_b1 + n);
                float v1 = acc[4*tl+1] + __ldg(out_b1 + n + 1);
                *(__half2*)(hTF + g*STW + n) = __floats2half2_rn(tanh_f(v0), tanh_f(v1));
            }
        }
        __syncthreads();

        // O2: out = t_o @ out_w2 + b2  (N=64, warps 0-7)
        if (wid < 8) {
            hgemm<256,1>(hTF, STW, c_ow2t, 256, wid*8, g, t4, acc);
            int n = wid*8 + 2*t4;
            float v0 = acc[0] + __ldg(out_b2 + n);
            float v1 = acc[1] + __ldg(out_b2 + n + 1);
            float* o = out + ((size_t)(m0 + g)*LYn + q)*YDd + n;
            o[0] = v0; o[1] = v1;
        }
        __syncthreads();
    }
}

// ---------------- launch ------------------------------------------------------
extern "C" void kernel_launch(void* const* d_in, const int* in_sizes, int n_in,
                              void* d_out, int out_size) {
    (void)in_sizes; (void)n_in; (void)out_size;
    const float* xd  = (const float*)d_in[0];
    const float* xm  = (const float*)d_in[1];
    const float* xt  = (const float*)d_in[2];
    const int*   xti = (const int*)d_in[3];
    const int*   yti = (const int*)d_in[4];

    const float* ug_w1 = (const float*)d_in[5];
    const float* ug_b1 = (const float*)d_in[6];
    const float* ug_w2 = (const float*)d_in[7];
    const float* ug_b2 = (const float*)d_in[8];
    const float* rg_w1 = (const float*)d_in[9];
    const float* rg_b1 = (const float*)d_in[10];
    const float* rg_w2 = (const float*)d_in[11];
    const float* rg_b2 = (const float*)d_in[12];
    const float* ns_w1 = (const float*)d_in[13];
    const float* ns_b1 = (const float*)d_in[14];
    const float* ns_w2 = (const float*)d_in[15];
    const float* ns_b2 = (const float*)d_in[16];
    const float* out_w1 = (const float*)d_in[17];
    const float* out_b1 = (const float*)d_in[18];
    const float* out_w2 = (const float*)d_in[19];
    const float* out_b2 = (const float*)d_in[20];
    const float* f_w1  = (const float*)d_in[21];
    const float* f_b1  = (const float*)d_in[22];
    const float* f_w2  = (const float*)d_in[23];
    const float* f_b2  = (const float*)d_in[24];

    cudaFuncSetAttribute(recur_kernel,
                         cudaFuncAttributeMaxDynamicSharedMemorySize, SMEM_BYTES);

    init_kernel<<<1, 256>>>(xt, xti, yti);
    conv_kernel<<<256, 256>>>(f_w1, f_w2, ug_w1, ug_w2, rg_w1, rg_w2,
                              ns_w1, ns_w2, out_w1, out_w2);

    recur_kernel<<<GRID, NTHR, SMEM_BYTES>>>(
        xd, xm,
        ug_b1, ug_b2, rg_b1, rg_b2, ns_b1, ns_b2,
        out_b1, out_b2, f_b1, f_b2,
        (float*)d_out);
}

// round 15
// speedup vs baseline: 2.8815x; 2.8815x over previous
#include <cuda_runtime.h>
#include <cuda_fp16.h>
#include <math.h>

// Problem constants (fixed by the dataset)
#define Bsz 1024
#define Tn  200
#define LXn 190
#define LYn 50
#define Hd  256
#define XDd 64
#define YDd 64

#define GRID 128
#define NTHR 512
#define ROWS 8

// row strides (in halves) for fp16 activation buffers
#define STW 264    // 256-wide buffers
#define STA 600    // 576-wide buffers

// ---------------- device scratch ---------------------------------------------
__device__ float g_dt[Tn];
__device__ int   g_obs[Tn];
__device__ int   g_qm [Tn];
// saved new_y at query steps, fp16 row-major per CTA: [q][cta][row(8)][col(256)]
__device__ __align__(16) __half g_ybh[(size_t)LYn*GRID*ROWS*Hd];

// fragment-packed fp16 weights: P[tile(n/8)][kc(k/16)][lane(32)][4 halves]
__device__ __align__(16) __half c_fw1p [256*256];
__device__ __align__(16) __half c_fw2p [256*256];
__device__ __align__(16) __half c_ugw1p[576*256];
__device__ __align__(16) __half c_ugw2p[256*256];
__device__ __align__(16) __half c_rgw1p[576*256];
__device__ __align__(16) __half c_rgw2p[256*256];
__device__ __align__(16) __half c_nsw1p[576*256];
__device__ __align__(16) __half c_nsw2p[256*512];
__device__ __align__(16) __half c_ow1p [256*256];
__device__ __align__(16) __half c_ow2p [256*64];

// ---------------- helpers -----------------------------------------------------
__device__ __forceinline__ float sigm(float x) {
    return __fdividef(1.0f, 1.0f + __expf(-x));
}
__device__ __forceinline__ float tanh_f(float x) {
    return fmaf(2.0f, sigm(2.0f*x), -1.0f);   // |err| ~1e-6 << budget
}

// m16n8k16 f16 MMA, fp32 accumulate. Rows 8-15 of A are zero (a1 = a3 = 0),
// so only c[0], c[1] (row g = lane>>2, cols 2t, 2t+1) are meaningful.
__device__ __forceinline__ void mma16(float* c, unsigned a0, unsigned a2,
                                      unsigned b0, unsigned b1) {
    asm volatile(
        "mma.sync.aligned.m16n8k16.row.col.f32.f16.f16.f32 "
        "{%0,%1,%2,%3}, {%4,%5,%6,%7}, {%8,%9}, {%0,%1,%2,%3};"
        : "+f"(c[0]), "+f"(c[1]), "+f"(c[2]), "+f"(c[3])
        : "r"(a0), "r"(0u), "r"(a2), "r"(0u), "r"(b0), "r"(b1));
}

// One warp computes NT n-tiles (8 cols each) over full K, in-register acc.
// A: smem fp16 [8 rows][strideA halves]; P: fragment-packed weights.
// Per mma: one coalesced LDG.64 delivers the whole warp's B fragment.
template<int K, int NT>
__device__ __forceinline__ void hgemm(const __half* A, int strideA,
                                      const __half* __restrict__ P,
                                      int tbase, int g, int t4, int lane,
                                      float* acc)
{
#pragma unroll
    for (int i = 0; i < NT*4; i++) acc[i] = 0.0f;
    const __half* arow = A + g*strideA + 2*t4;
    const uint2* pp[NT];
#pragma unroll
    for (int tl = 0; tl < NT; tl++)
        pp[tl] = (const uint2*)P + ((size_t)(tbase + tl)*(K/16))*32 + lane;
#pragma unroll 2
    for (int ck = 0; ck < K/16; ck++) {
        unsigned a0 = *(const unsigned*)(arow + ck*16);
        unsigned a2 = *(const unsigned*)(arow + ck*16 + 8);
#pragma unroll
        for (int tl = 0; tl < NT; tl++) {
            uint2 b = __ldg(pp[tl] + ck*32);
            mma16(acc + 4*tl, a0, a2, b.x, b.y);
        }
    }
}

// ---------------- init: dt / obs-slot / query maps ---------------------------
__global__ void init_kernel(const float* __restrict__ x_time,
                            const int* __restrict__ x_idx,
                            const int* __restrict__ y_idx) {
    int tid = threadIdx.x;
    for (int t = tid; t < Tn; t += blockDim.x) { g_obs[t] = -1; g_qm[t] = -1; }
    __syncthreads();
    for (int i = tid; i < LXn; i += blockDim.x) g_obs[x_idx[i]] = i;
    for (int j = tid; j < LYn; j += blockDim.x) g_qm[y_idx[j]] = j;
    __syncthreads();
    for (int t = tid; t < Tn; t += blockDim.x) {
        float d;
        float tlast = x_time[Tn - 1];
        if (t == 0)      d = tlast - (tlast + 0.01f);
        else if (t == 1) d = tlast - x_time[0];
        else             d = x_time[t - 2] - x_time[t - 1];
        g_dt[t] = d;
    }
}

// ---------------- conv: fp32 [k][N] -> fragment-packed fp16 -------------------
// dst element e (4 halves): t=e&31, c=e>>5, kc=c%(K/16), tn=c/(K/16);
//   n = tn*8 + (t>>2), kk = 2*(t&3):
//   j0 = W[kc*16+kk][n], j1 = W[kc*16+kk+1][n],
//   j2 = W[kc*16+8+kk][n], j3 = W[kc*16+8+kk+1][n]
__device__ void convP(__half* dst, const float* __restrict__ src, int K, int N,
                      int g0, int gs) {
    int KC = K / 16;
    int tot = (N/8) * KC * 32;
    for (int e = g0; e < tot; e += gs) {
        int t = e & 31, c = e >> 5;
        int kc = c % KC, tn = c / KC;
        int n = tn*8 + (t >> 2);
        int k = kc*16 + 2*(t & 3);
        dst[(size_t)e*4 + 0] = __float2half_rn(src[(size_t)k*N + n]);
        dst[(size_t)e*4 + 1] = __float2half_rn(src[(size_t)(k + 1)*N + n]);
        dst[(size_t)e*4 + 2] = __float2half_rn(src[(size_t)(k + 8)*N + n]);
        dst[(size_t)e*4 + 3] = __float2half_rn(src[(size_t)(k + 9)*N + n]);
    }
}
__global__ void conv_kernel(const float* fw1, const float* fw2,
                            const float* ugw1, const float* ugw2,
                            const float* rgw1, const float* rgw2,
                            const float* nsw1, const float* nsw2,
                            const float* ow1, const float* ow2) {
    int g0 = blockIdx.x*blockDim.x + threadIdx.x;
    int gs = gridDim.x*blockDim.x;
    convP(c_fw1p,  fw1,  256, 256, g0, gs);
    convP(c_fw2p,  fw2,  256, 256, g0, gs);
    convP(c_ugw1p, ugw1, 576, 256, g0, gs);
    convP(c_ugw2p, ugw2, 256, 256, g0, gs);
    convP(c_rgw1p, rgw1, 576, 256, g0, gs);
    convP(c_rgw2p, rgw2, 256, 256, g0, gs);
    convP(c_nsw1p, nsw1, 576, 256, g0, gs);
    convP(c_nsw2p, nsw2, 256, 512, g0, gs);
    convP(c_ow1p,  ow1,  256, 256, g0, gs);
    convP(c_ow2p,  ow2,  256, 64,  g0, gs);
}

// ---------------- smem layout --------------------------------------------------
#define SMEM_BYTES (2*(2*4800) + 2*(6*2112) + 4*8192)   // 77312

// ---------------- persistent per-CTA recurrence (HMMA, packed weights) ---------
__global__ void __launch_bounds__(NTHR, 1)
recur_kernel(const float* __restrict__ xd, const float* __restrict__ xm,
             const float* __restrict__ ug_b1, const float* __restrict__ ug_b2,
             const float* __restrict__ rg_b1, const float* __restrict__ rg_b2,
             const float* __restrict__ ns_b1, const float* __restrict__ ns_b2,
             const float* __restrict__ out_b1, const float* __restrict__ out_b2,
             const float* __restrict__ f_b1, const float* __restrict__ f_b2,
             float* __restrict__ out)
{
    extern __shared__ __align__(16) char smraw[];
    __half* hA  = (__half*)smraw;            // [8][600] cat(hi, s, x)
    __half* hC  = hA  + 4800;                // [8][600] cat(c1, c2, x)
    __half* hH  = hC  + 4800;                // [8][264] each below
    __half* hTF = hH  + 2112;
    __half* hTU = hTF + 2112;
    __half* hTR = hTU + 2112;
    __half* hTN = hTR + 2112;
    __half* hYB = hTN + 2112;
    float*  sHf  = (float*)(hYB + 2112);     // [8][256] each
    float*  sSf  = sHf  + 2048;
    float*  sHIf = sSf  + 2048;
    float*  sUf  = sHIf + 2048;

    const int tid  = threadIdx.x;
    const int wid  = tid >> 5;
    const int lane = tid & 31;
    const int g    = lane >> 2;   // row 0..7 / D-row
    const int t4   = lane & 3;    // D col pair
    const int cta  = blockIdx.x;
    const int m0   = cta * ROWS;

    // zero initial state
    for (int i = tid; i < 2048; i += NTHR) {
        sHf[i] = 0.0f; sSf[i] = 0.0f;
        int r = i >> 8, c = i & 255;
        hH[r*STW + c] = __float2half(0.0f);
        hA[r*STA + 256 + c] = __float2half(0.0f);
    }
    __syncthreads();

    float acc[16];

    for (int tstep = 0; tstep < Tn; tstep++) {
        const int   obs = g_obs[tstep];
        const int   q   = g_qm[tstep];
        const float dt  = g_dt[tstep];

        // ---- prologue: x -> hA/hC[512:576] (fp16) ----
        if (tid < XDd) {
            for (int r = 0; r < 8; r++) {
                float xv = 0.0f;
                if (obs >= 0) {
                    int off = ((m0 + r)*LXn + obs)*XDd + tid;
                    xv = __ldg(xd + off) * __ldg(xm + off);
                }
                __half h = __float2half_rn(xv);
                hA[r*STA + 512 + tid] = h;
                hC[r*STA + 512 + tid] = h;
            }
        }
        // (first consumer is S3/S5 — syncs in between)

        // ---- S1: tf = tanh(h @ f_w1 + b1)  [N=256, 2 tiles/warp] ----
        hgemm<256,2>(hH, STW, c_fw1p, wid*2, g, t4, lane, acc);
        {
#pragma unroll
            for (int tl = 0; tl < 2; tl++) {
                int n = wid*16 + tl*8 + 2*t4;
                float v0 = acc[4*tl]   + __ldg(f_b1 + n);
                float v1 = acc[4*tl+1] + __ldg(f_b1 + n + 1);
                *(__half2*)(hTF + g*STW + n) = __floats2half2_rn(tanh_f(v0), tanh_f(v1));
            }
        }
        __syncthreads();

        // ---- S2: hi = h + dt*(tf @ f_w2 + b2) -> hA[0:256] + sHIf ----
        hgemm<256,2>(hTF, STW, c_fw2p, wid*2, g, t4, lane, acc);
        {
#pragma unroll
            for (int tl = 0; tl < 2; tl++) {
                int n = wid*16 + tl*8 + 2*t4;
                float2 h2 = *(float2*)(sHf + g*256 + n);
                float hi0 = h2.x + dt*(acc[4*tl]   + __ldg(f_b2 + n));
                float hi1 = h2.y + dt*(acc[4*tl+1] + __ldg(f_b2 + n + 1));
                *(__half2*)(hA + g*STA + n) = __floats2half2_rn(hi0, hi1);
                *(float2*)(sHIf + g*256 + n) = make_float2(hi0, hi1);
            }
        }
        __syncthreads();

        // ---- S3: tu / tr = tanh(cat(hi,s,x) @ {ug,rg}_w1 + b)  [K=576] ----
        {
            const bool isr = (wid >= 8);
            int wb = isr ? (wid - 8) : wid;
            hgemm<576,4>(hA, STA, isr ? c_rgw1p : c_ugw1p, wb*4, g, t4, lane, acc);
            const float* bias = isr ? rg_b1 : ug_b1;
            __half* dst = isr ? hTR : hTU;
#pragma unroll
            for (int tl = 0; tl < 4; tl++) {
                int n = wb*32 + tl*8 + 2*t4;
                float v0 = acc[4*tl]   + __ldg(bias + n);
                float v1 = acc[4*tl+1] + __ldg(bias + n + 1);
                *(__half2*)(dst + g*STW + n) = __floats2half2_rn(tanh_f(v0), tanh_f(v1));
            }
        }
        __syncthreads();

        // ---- S4: u = sig(tu@ug_w2+b); r = sig(tr@rg_w2+b); c1=hi*r; c2=s*r ----
        {
            float ar[8];
            hgemm<256,2>(hTU, STW, c_ugw2p, wid*2, g, t4, lane, acc);
            hgemm<256,2>(hTR, STW, c_rgw2p, wid*2, g, t4, lane, ar);
#pragma unroll
            for (int tl = 0; tl < 2; tl++) {
                int n = wid*16 + tl*8 + 2*t4;
                float u0 = sigm(acc[4*tl]   + __ldg(ug_b2 + n));
                float u1 = sigm(acc[4*tl+1] + __ldg(ug_b2 + n + 1));
                float r0 = sigm(ar[4*tl]    + __ldg(rg_b2 + n));
                float r1 = sigm(ar[4*tl+1]  + __ldg(rg_b2 + n + 1));
                float2 hi = *(float2*)(sHIf + g*256 + n);
                float2 ss = *(float2*)(sSf  + g*256 + n);
                *(float2*)(sUf + g*256 + n) = make_float2(u0, u1);
                *(__half2*)(hC + g*STA + n)       = __floats2half2_rn(hi.x*r0, hi.y*r1);
                *(__half2*)(hC + g*STA + 256 + n) = __floats2half2_rn(ss.x*r0, ss.y*r1);
            }
        }
        __syncthreads();

        // ---- S5: tn = tanh(cat(c1,c2,x) @ ns_w1 + b)  [K=576, N=256] ----
        hgemm<576,2>(hC, STA, c_nsw1p, wid*2, g, t4, lane, acc);
        {
#pragma unroll
            for (int tl = 0; tl < 2; tl++) {
                int n = wid*16 + tl*8 + 2*t4;
                float v0 = acc[4*tl]   + __ldg(ns_b1 + n);
                float v1 = acc[4*tl+1] + __ldg(ns_b1 + n + 1);
                *(__half2*)(hTN + g*STW + n) = __floats2half2_rn(tanh_f(v0), tanh_f(v1));
            }
        }
        __syncthreads();

        // ---- S6: ns | std (N=512), gated state update ----
        {
            const bool sd = (wid >= 8);
            int nb = sd ? 256 + (wid - 8)*32 : wid*32;
            hgemm<256,4>(hTN, STW, c_nsw2p, nb >> 3, g, t4, lane, acc);
#pragma unroll
            for (int tl = 0; tl < 4; tl++) {
                int n = nb + tl*8 + 2*t4;
                float v0 = acc[4*tl]   + __ldg(ns_b2 + n);
                float v1 = acc[4*tl+1] + __ldg(ns_b2 + n + 1);
                if (!sd) {
                    float2 u  = *(float2*)(sUf  + g*256 + n);
                    float2 hi = *(float2*)(sHIf + g*256 + n);
                    float hy0 = (1.0f - u.x)*v0 + u.x*hi.x;
                    float hy1 = (1.0f - u.y)*v1 + u.y*hi.y;
                    *(float2*)(sHf + g*256 + n) = make_float2(hy0, hy1);
                    __half2 hp = __floats2half2_rn(hy0, hy1);
                    *(__half2*)(hH + g*STW + n) = hp;
                    if (q >= 0)
                        *(__half2*)(g_ybh + (((size_t)q*GRID + cta)*ROWS + g)*Hd + n) = hp;
                } else {
                    int nn = n - 256;
                    float2 u  = *(float2*)(sUf + g*256 + nn);
                    float2 ss = *(float2*)(sSf + g*256 + nn);
                    float sy0 = fabsf((1.0f - u.x)*fabsf(v0) + u.x*ss.x);
                    float sy1 = fabsf((1.0f - u.y)*fabsf(v1) + u.y*ss.y);
                    *(float2*)(sSf + g*256 + nn) = make_float2(sy0, sy1);
                    *(__half2*)(hA + g*STA + 256 + nn) = __floats2half2_rn(sy0, sy1);
                }
            }
        }
        __syncthreads();
    }

    // ---- deferred out-MLP over the 50 saved query states ----
    for (int q = 0; q < LYn; q++) {
        {
            const unsigned* src = (const unsigned*)(g_ybh + ((size_t)q*GRID + cta)*ROWS*Hd);
            for (int i = tid; i < 1024; i += NTHR) {
                int r = i >> 7, pr = i & 127;
                *(unsigned*)(hYB + r*STW + pr*2) = src[r*128 + pr];
            }
        }
        __syncthreads();

        // O1: t_o = tanh(yb @ out_w1 + b1)
        hgemm<256,2>(hYB, STW, c_ow1p, wid*2, g, t4, lane, acc);
        {
#pragma unroll
            for (int tl = 0; tl < 2; tl++) {
                int n = wid*16 + tl*8 + 2*t4;
                float v0 = acc[4*tl]   + __ldg(out_b1 + n);
                float v1 = acc[4*tl+1] + __ldg(out_b1 + n + 1);
                *(__half2*)(hTF + g*STW + n) = __floats2half2_rn(tanh_f(v0), tanh_f(v1));
            }
        }
        __syncthreads();

        // O2: out = t_o @ out_w2 + b2  (N=64, warps 0-7)
        if (wid < 8) {
            hgemm<256,1>(hTF, STW, c_ow2p, wid, g, t4, lane, acc);
            int n = wid*8 + 2*t4;
            float v0 = acc[0] + __ldg(out_b2 + n);
            float v1 = acc[1] + __ldg(out_b2 + n + 1);
            float* o = out + ((size_t)(m0 + g)*LYn + q)*YDd + n;
            o[0] = v0; o[1] = v1;
        }
        __syncthreads();
    }
}

// ---------------- launch ------------------------------------------------------
extern "C" void kernel_launch(void* const* d_in, const int* in_sizes, int n_in,
                              void* d_out, int out_size) {
    (void)in_sizes; (void)n_in; (void)out_size;
    const float* xd  = (const float*)d_in[0];
    const float* xm  = (const float*)d_in[1];
    const float* xt  = (const float*)d_in[2];
    const int*   xti = (const int*)d_in[3];
    const int*   yti = (const int*)d_in[4];

    const float* ug_w1 = (const float*)d_in[5];
    const float* ug_b1 = (const float*)d_in[6];
    const float* ug_w2 = (const float*)d_in[7];
    const float* ug_b2 = (const float*)d_in[8];
    const float* rg_w1 = (const float*)d_in[9];
    const float* rg_b1 = (const float*)d_in[10];
    const float* rg_w2 = (const float*)d_in[11];
    const float* rg_b2 = (const float*)d_in[12];
    const float* ns_w1 = (const float*)d_in[13];
    const float* ns_b1 = (const float*)d_in[14];
    const float* ns_w2 = (const float*)d_in[15];
    const float* ns_b2 = (const float*)d_in[16];
    const float* out_w1 = (const float*)d_in[17];
    const float* out_b1 = (const float*)d_in[18];
    const float* out_w2 = (const float*)d_in[19];
    const float* out_b2 = (const float*)d_in[20];
    const float* f_w1  = (const float*)d_in[21];
    const float* f_b1  = (const float*)d_in[22];
    const float* f_w2  = (const float*)d_in[23];
    const float* f_b2  = (const float*)d_in[24];

    cudaFuncSetAttribute(recur_kernel,
                         cudaFuncAttributeMaxDynamicSharedMemorySize, SMEM_BYTES);

    init_kernel<<<1, 256>>>(xt, xti, yti);
    conv_kernel<<<256, 256>>>(f_w1, f_w2, ug_w1, ug_w2, rg_w1, rg_w2,
                              ns_w1, ns_w2, out_w1, out_w2);

    recur_kernel<<<GRID, NTHR, SMEM_BYTES>>>(
        xd, xm,
        ug_b1, ug_b2, rg_b1, rg_b2, ns_b1, ns_b2,
        out_b1, out_b2, f_b1, f_b2,
        (float*)d_out);
}

// round 16
// speedup vs baseline: 3.2712x; 1.1352x over previous
#include <cuda_runtime.h>
#include <cuda_fp16.h>
#include <math.h>

// Problem constants (fixed by the dataset)
#define Bsz 1024
#define Tn  200
#define LXn 190
#define LYn 50
#define Hd  256
#define XDd 64
#define YDd 64

#define GRID 128
#define NTHR 512
#define ROWS 8

// row strides (in halves) for fp16 activation buffers
#define STW 264    // 256-wide buffers
#define STA 600    // 576-wide buffers

// ---------------- device scratch ---------------------------------------------
__device__ float g_dt[Tn];
__device__ int   g_obs[Tn];
__device__ int   g_qm [Tn];
// saved new_y at query steps, fp16 row-major per CTA: [q][cta][row(8)][col(256)]
__device__ __align__(16) __half g_ybh[(size_t)LYn*GRID*ROWS*Hd];

// fragment-packed fp16 weights: P[tile(n/8)][kc(k/16)][lane(32)][4 halves]
__device__ __align__(16) __half c_fw1p [256*256];
__device__ __align__(16) __half c_fw2p [256*256];
__device__ __align__(16) __half c_ugw1p[576*256];
__device__ __align__(16) __half c_ugw2p[256*256];
__device__ __align__(16) __half c_rgw1p[576*256];
__device__ __align__(16) __half c_rgw2p[256*256];
__device__ __align__(16) __half c_nsw1p[576*256];
__device__ __align__(16) __half c_nsw2p[256*512];
__device__ __align__(16) __half c_ow1p [256*256];
__device__ __align__(16) __half c_ow2p [256*64];

// ---------------- helpers -----------------------------------------------------
__device__ __forceinline__ float sigm(float x) {
    return __fdividef(1.0f, 1.0f + __expf(-x));
}
__device__ __forceinline__ float tanh_f(float x) {
    return fmaf(2.0f, sigm(2.0f*x), -1.0f);   // |err| ~1e-6 << budget
}

// m16n8k16 f16 MMA, fp32 accumulate; A rows 8-15 zero (half-M variant).
__device__ __forceinline__ void mma16(float* c, unsigned a0, unsigned a2,
                                      unsigned b0, unsigned b1) {
    asm volatile(
        "mma.sync.aligned.m16n8k16.row.col.f32.f16.f16.f32 "
        "{%0,%1,%2,%3}, {%4,%5,%6,%7}, {%8,%9}, {%0,%1,%2,%3};"
        : "+f"(c[0]), "+f"(c[1]), "+f"(c[2]), "+f"(c[3])
        : "r"(a0), "r"(0u), "r"(a2), "r"(0u), "r"(b0), "r"(b1));
}
// full m16 variant (all 16 A rows live)
__device__ __forceinline__ void mma16f(float* c, unsigned a0, unsigned a1,
                                       unsigned a2, unsigned a3,
                                       unsigned b0, unsigned b1) {
    asm volatile(
        "mma.sync.aligned.m16n8k16.row.col.f32.f16.f16.f32 "
        "{%0,%1,%2,%3}, {%4,%5,%6,%7}, {%8,%9}, {%0,%1,%2,%3};"
        : "+f"(c[0]), "+f"(c[1]), "+f"(c[2]), "+f"(c[3])
        : "r"(a0), "r"(a1), "r"(a2), "r"(a3), "r"(b0), "r"(b1));
}

// One warp computes NT n-tiles (8 cols each) over full K, in-register acc.
// Explicit double-buffered prefetch of A-pair and all NT B-fragments.
template<int K, int NT>
__device__ __forceinline__ void hgemm(const __half* A, int strideA,
                                      const __half* __restrict__ P,
                                      int tbase, int g, int t4, int lane,
                                      float* acc)
{
    const int KC = K / 16;
#pragma unroll
    for (int i = 0; i < NT*4; i++) acc[i] = 0.0f;
    const __half* arow = A + g*strideA + 2*t4;
    const uint2* pbase = (const uint2*)P + (size_t)tbase*KC*32 + lane;

    unsigned a0 = *(const unsigned*)(arow);
    unsigned a2 = *(const unsigned*)(arow + 8);
    uint2 bb[NT];
#pragma unroll
    for (int tl = 0; tl < NT; tl++) bb[tl] = __ldg(pbase + (size_t)tl*KC*32);

#pragma unroll 2
    for (int ck = 0; ck < KC - 1; ck++) {
        unsigned na0 = *(const unsigned*)(arow + (ck + 1)*16);
        unsigned na2 = *(const unsigned*)(arow + (ck + 1)*16 + 8);
        uint2 nb[NT];
#pragma unroll
        for (int tl = 0; tl < NT; tl++)
            nb[tl] = __ldg(pbase + (size_t)tl*KC*32 + (ck + 1)*32);
#pragma unroll
        for (int tl = 0; tl < NT; tl++)
            mma16(acc + 4*tl, a0, a2, bb[tl].x, bb[tl].y);
        a0 = na0; a2 = na2;
#pragma unroll
        for (int tl = 0; tl < NT; tl++) bb[tl] = nb[tl];
    }
#pragma unroll
    for (int tl = 0; tl < NT; tl++)
        mma16(acc + 4*tl, a0, a2, bb[tl].x, bb[tl].y);
}

// Full-M (16-row A) variant for the paired-query out-MLP.
template<int K, int NT>
__device__ __forceinline__ void hgemm16(const __half* A, int strideA,
                                        const __half* __restrict__ P,
                                        int tbase, int g, int t4, int lane,
                                        float* acc)
{
    const int KC = K / 16;
#pragma unroll
    for (int i = 0; i < NT*4; i++) acc[i] = 0.0f;
    const __half* arow0 = A + g*strideA + 2*t4;
    const __half* arow1 = A + (g + 8)*strideA + 2*t4;
    const uint2* pbase = (const uint2*)P + (size_t)tbase*KC*32 + lane;
#pragma unroll 2
    for (int ck = 0; ck < KC; ck++) {
        unsigned a0 = *(const unsigned*)(arow0 + ck*16);
        unsigned a1 = *(const unsigned*)(arow1 + ck*16);
        unsigned a2 = *(const unsigned*)(arow0 + ck*16 + 8);
        unsigned a3 = *(const unsigned*)(arow1 + ck*16 + 8);
#pragma unroll
        for (int tl = 0; tl < NT; tl++) {
            uint2 b = __ldg(pbase + (size_t)tl*KC*32 + ck*32);
            mma16f(acc + 4*tl, a0, a1, a2, a3, b.x, b.y);
        }
    }
}

// ---------------- init: dt / obs-slot / query maps ---------------------------
__global__ void init_kernel(const float* __restrict__ x_time,
                            const int* __restrict__ x_idx,
                            const int* __restrict__ y_idx) {
    int tid = threadIdx.x;
    for (int t = tid; t < Tn; t += blockDim.x) { g_obs[t] = -1; g_qm[t] = -1; }
    __syncthreads();
    for (int i = tid; i < LXn; i += blockDim.x) g_obs[x_idx[i]] = i;
    for (int j = tid; j < LYn; j += blockDim.x) g_qm[y_idx[j]] = j;
    __syncthreads();
    for (int t = tid; t < Tn; t += blockDim.x) {
        float d;
        float tlast = x_time[Tn - 1];
        if (t == 0)      d = tlast - (tlast + 0.01f);
        else if (t == 1) d = tlast - x_time[0];
        else             d = x_time[t - 2] - x_time[t - 1];
        g_dt[t] = d;
    }
}

// ---------------- conv: fp32 [k][N] -> fragment-packed fp16 -------------------
__device__ void convP(__half* dst, const float* __restrict__ src, int K, int N,
                      int g0, int gs) {
    int KC = K / 16;
    int tot = (N/8) * KC * 32;
    for (int e = g0; e < tot; e += gs) {
        int t = e & 31, c = e >> 5;
        int kc = c % KC, tn = c / KC;
        int n = tn*8 + (t >> 2);
        int k = kc*16 + 2*(t & 3);
        dst[(size_t)e*4 + 0] = __float2half_rn(src[(size_t)k*N + n]);
        dst[(size_t)e*4 + 1] = __float2half_rn(src[(size_t)(k + 1)*N + n]);
        dst[(size_t)e*4 + 2] = __float2half_rn(src[(size_t)(k + 8)*N + n]);
        dst[(size_t)e*4 + 3] = __float2half_rn(src[(size_t)(k + 9)*N + n]);
    }
}
__global__ void conv_kernel(const float* fw1, const float* fw2,
                            const float* ugw1, const float* ugw2,
                            const float* rgw1, const float* rgw2,
                            const float* nsw1, const float* nsw2,
                            const float* ow1, const float* ow2) {
    int g0 = blockIdx.x*blockDim.x + threadIdx.x;
    int gs = gridDim.x*blockDim.x;
    convP(c_fw1p,  fw1,  256, 256, g0, gs);
    convP(c_fw2p,  fw2,  256, 256, g0, gs);
    convP(c_ugw1p, ugw1, 576, 256, g0, gs);
    convP(c_ugw2p, ugw2, 256, 256, g0, gs);
    convP(c_rgw1p, rgw1, 576, 256, g0, gs);
    convP(c_rgw2p, rgw2, 256, 256, g0, gs);
    convP(c_nsw1p, nsw1, 576, 256, g0, gs);
    convP(c_nsw2p, nsw2, 256, 512, g0, gs);
    convP(c_ow1p,  ow1,  256, 256, g0, gs);
    convP(c_ow2p,  ow2,  256, 64,  g0, gs);
}

// ---------------- smem layout --------------------------------------------------
// halves: hA[8][600], hC[8][600], hH/hTF/hTU/hTR/hTN [8][264], hYB [16][264]
//   (hTF and hTU are contiguous -> together form a 16-row [16][264] buffer)
// floats: sHf, sSf, sHIf, sUf [8][256]
#define SMEM_BYTES (2*(2*4800 + 5*2112 + 4224) + 4*8192)   // 81536

// ---------------- persistent per-CTA recurrence (HMMA, packed weights) ---------
__global__ void __launch_bounds__(NTHR, 1)
recur_kernel(const float* __restrict__ xd, const float* __restrict__ xm,
             const float* __restrict__ ug_b1, const float* __restrict__ ug_b2,
             const float* __restrict__ rg_b1, const float* __restrict__ rg_b2,
             const float* __restrict__ ns_b1, const float* __restrict__ ns_b2,
             const float* __restrict__ out_b1, const float* __restrict__ out_b2,
             const float* __restrict__ f_b1, const float* __restrict__ f_b2,
             float* __restrict__ out)
{
    extern __shared__ __align__(16) char smraw[];
    __half* hA  = (__half*)smraw;            // [8][600] cat(hi, s, x)
    __half* hC  = hA  + 4800;                // [8][600] cat(c1, c2, x)
    __half* hH  = hC  + 4800;                // [8][264]
    __half* hTF = hH  + 2112;                // [8][264]  (+hTU = 16-row buffer)
    __half* hTU = hTF + 2112;                // [8][264]
    __half* hTR = hTU + 2112;                // [8][264]
    __half* hTN = hTR + 2112;                // [8][264]
    __half* hYB = hTN + 2112;                // [16][264]
    float*  sHf  = (float*)(hYB + 4224);     // [8][256] each
    float*  sSf  = sHf  + 2048;
    float*  sHIf = sSf  + 2048;
    float*  sUf  = sHIf + 2048;

    const int tid  = threadIdx.x;
    const int wid  = tid >> 5;
    const int lane = tid & 31;
    const int g    = lane >> 2;   // D-row 0..7
    const int t4   = lane & 3;    // D col pair
    const int cta  = blockIdx.x;
    const int m0   = cta * ROWS;

    // zero initial state
    for (int i = tid; i < 2048; i += NTHR) {
        sHf[i] = 0.0f; sSf[i] = 0.0f;
        int r = i >> 8, c = i & 255;
        hH[r*STW + c] = __float2half(0.0f);
        hA[r*STA + 256 + c] = __float2half(0.0f);
    }
    __syncthreads();

    float acc[16];

    for (int tstep = 0; tstep < Tn; tstep++) {
        const int   obs = g_obs[tstep];
        const int   q   = g_qm[tstep];
        const float dt  = g_dt[tstep];

        // ---- prologue: x -> hA/hC[512:576] (fp16); overlaps with S1 ----
        if (tid < XDd) {
            for (int r = 0; r < 8; r++) {
                float xv = 0.0f;
                if (obs >= 0) {
                    int off = ((m0 + r)*LXn + obs)*XDd + tid;
                    xv = __ldg(xd + off) * __ldg(xm + off);
                }
                __half h = __float2half_rn(xv);
                hA[r*STA + 512 + tid] = h;
                hC[r*STA + 512 + tid] = h;
            }
        }

        // ---- S1: tf = tanh(h @ f_w1 + b1)  [N=256, 2 tiles/warp] ----
        hgemm<256,2>(hH, STW, c_fw1p, wid*2, g, t4, lane, acc);
        {
#pragma unroll
            for (int tl = 0; tl < 2; tl++) {
                int n = wid*16 + tl*8 + 2*t4;
                float v0 = acc[4*tl]   + __ldg(f_b1 + n);
                float v1 = acc[4*tl+1] + __ldg(f_b1 + n + 1);
                *(__half2*)(hTF + g*STW + n) = __floats2half2_rn(tanh_f(v0), tanh_f(v1));
            }
        }
        __syncthreads();

        // ---- S2: hi = h + dt*(tf @ f_w2 + b2) -> hA[0:256] + sHIf ----
        hgemm<256,2>(hTF, STW, c_fw2p, wid*2, g, t4, lane, acc);
        {
#pragma unroll
            for (int tl = 0; tl < 2; tl++) {
                int n = wid*16 + tl*8 + 2*t4;
                float2 h2 = *(float2*)(sHf + g*256 + n);
                float hi0 = h2.x + dt*(acc[4*tl]   + __ldg(f_b2 + n));
                float hi1 = h2.y + dt*(acc[4*tl+1] + __ldg(f_b2 + n + 1));
                *(__half2*)(hA + g*STA + n) = __floats2half2_rn(hi0, hi1);
                *(float2*)(sHIf + g*256 + n) = make_float2(hi0, hi1);
            }
        }
        __syncthreads();

        // ---- S3: tu / tr = tanh(cat(hi,s,x) @ {ug,rg}_w1 + b)  [K=576] ----
        {
            const bool isr = (wid >= 8);
            int wb = isr ? (wid - 8) : wid;
            hgemm<576,4>(hA, STA, isr ? c_rgw1p : c_ugw1p, wb*4, g, t4, lane, acc);
            const float* bias = isr ? rg_b1 : ug_b1;
            __half* dst = isr ? hTR : hTU;
#pragma unroll
            for (int tl = 0; tl < 4; tl++) {
                int n = wb*32 + tl*8 + 2*t4;
                float v0 = acc[4*tl]   + __ldg(bias + n);
                float v1 = acc[4*tl+1] + __ldg(bias + n + 1);
                *(__half2*)(dst + g*STW + n) = __floats2half2_rn(tanh_f(v0), tanh_f(v1));
            }
        }
        __syncthreads();

        // ---- S4: u = sig(tu@ug_w2+b); r = sig(tr@rg_w2+b); c1=hi*r; c2=s*r ----
        {
            float ar[8];
            hgemm<256,2>(hTU, STW, c_ugw2p, wid*2, g, t4, lane, acc);
            hgemm<256,2>(hTR, STW, c_rgw2p, wid*2, g, t4, lane, ar);
#pragma unroll
            for (int tl = 0; tl < 2; tl++) {
                int n = wid*16 + tl*8 + 2*t4;
                float u0 = sigm(acc[4*tl]   + __ldg(ug_b2 + n));
                float u1 = sigm(acc[4*tl+1] + __ldg(ug_b2 + n + 1));
                float r0 = sigm(ar[4*tl]    + __ldg(rg_b2 + n));
                float r1 = sigm(ar[4*tl+1]  + __ldg(rg_b2 + n + 1));
                float2 hi = *(float2*)(sHIf + g*256 + n);
                float2 ss = *(float2*)(sSf  + g*256 + n);
                *(float2*)(sUf + g*256 + n) = make_float2(u0, u1);
                *(__half2*)(hC + g*STA + n)       = __floats2half2_rn(hi.x*r0, hi.y*r1);
                *(__half2*)(hC + g*STA + 256 + n) = __floats2half2_rn(ss.x*r0, ss.y*r1);
            }
        }
        __syncthreads();

        // ---- S5: tn = tanh(cat(c1,c2,x) @ ns_w1 + b)  [K=576, N=256] ----
        hgemm<576,2>(hC, STA, c_nsw1p, wid*2, g, t4, lane, acc);
        {
#pragma unroll
            for (int tl = 0; tl < 2; tl++) {
                int n = wid*16 + tl*8 + 2*t4;
                float v0 = acc[4*tl]   + __ldg(ns_b1 + n);
                float v1 = acc[4*tl+1] + __ldg(ns_b1 + n + 1);
                *(__half2*)(hTN + g*STW + n) = __floats2half2_rn(tanh_f(v0), tanh_f(v1));
            }
        }
        __syncthreads();

        // ---- S6: ns | std (N=512), gated state update ----
        {
            const bool sd = (wid >= 8);
            int nb = sd ? 256 + (wid - 8)*32 : wid*32;
            hgemm<256,4>(hTN, STW, c_nsw2p, nb >> 3, g, t4, lane, acc);
#pragma unroll
            for (int tl = 0; tl < 4; tl++) {
                int n = nb + tl*8 + 2*t4;
                float v0 = acc[4*tl]   + __ldg(ns_b2 + n);
                float v1 = acc[4*tl+1] + __ldg(ns_b2 + n + 1);
                if (!sd) {
                    float2 u  = *(float2*)(sUf  + g*256 + n);
                    float2 hi = *(float2*)(sHIf + g*256 + n);
                    float hy0 = (1.0f - u.x)*v0 + u.x*hi.x;
                    float hy1 = (1.0f - u.y)*v1 + u.y*hi.y;
                    *(float2*)(sHf + g*256 + n) = make_float2(hy0, hy1);
                    __half2 hp = __floats2half2_rn(hy0, hy1);
                    *(__half2*)(hH + g*STW + n) = hp;
                    if (q >= 0)
                        *(__half2*)(g_ybh + (((size_t)q*GRID + cta)*ROWS + g)*Hd + n) = hp;
                } else {
                    int nn = n - 256;
                    float2 u  = *(float2*)(sUf + g*256 + nn);
                    float2 ss = *(float2*)(sSf + g*256 + nn);
                    float sy0 = fabsf((1.0f - u.x)*fabsf(v0) + u.x*ss.x);
                    float sy1 = fabsf((1.0f - u.y)*fabsf(v1) + u.y*ss.y);
                    *(float2*)(sSf + g*256 + nn) = make_float2(sy0, sy1);
                    *(__half2*)(hA + g*STA + 256 + nn) = __floats2half2_rn(sy0, sy1);
                }
            }
        }
        __syncthreads();
    }

    // ---- deferred out-MLP: queries processed in pairs (full m16) ----
    for (int qp = 0; qp < LYn; qp += 2) {
        // rows 0-7 <- query qp, rows 8-15 <- query qp+1
        for (int i = tid; i < 2048; i += NTHR) {
            int r = i >> 7, pr = i & 127;
            int qs = qp + (r >> 3), row = r & 7;
            const unsigned* src =
                (const unsigned*)(g_ybh + ((size_t)qs*GRID + cta)*ROWS*Hd);
            *(unsigned*)(hYB + r*STW + pr*2) = src[row*128 + pr];
        }
        __syncthreads();

        // O1: t_o = tanh(yb @ out_w1 + b1)  -> hTF (16 rows via hTF+hTU)
        hgemm16<256,2>(hYB, STW, c_ow1p, wid*2, g, t4, lane, acc);
        {
#pragma unroll
            for (int tl = 0; tl < 2; tl++) {
                int n = wid*16 + tl*8 + 2*t4;
                float b0 = __ldg(out_b1 + n), b1 = __ldg(out_b1 + n + 1);
                *(__half2*)(hTF + g*STW + n) =
                    __floats2half2_rn(tanh_f(acc[4*tl] + b0), tanh_f(acc[4*tl+1] + b1));
                *(__half2*)(hTF + (g + 8)*STW + n) =
                    __floats2half2_rn(tanh_f(acc[4*tl+2] + b0), tanh_f(acc[4*tl+3] + b1));
            }
        }
        __syncthreads();

        // O2: out = t_o @ out_w2 + b2  (N=64, warps 0-7; both queries at once)
        if (wid < 8) {
            hgemm16<256,1>(hTF, STW, c_ow2p, wid, g, t4, lane, acc);
            int n = wid*8 + 2*t4;
            float b0 = __ldg(out_b2 + n), b1 = __ldg(out_b2 + n + 1);
            float* o0 = out + ((size_t)(m0 + g)*LYn + qp)*YDd + n;
            o0[0] = acc[0] + b0; o0[1] = acc[1] + b1;
            float* o1 = out + ((size_t)(m0 + g)*LYn + qp + 1)*YDd + n;
            o1[0] = acc[2] + b0; o1[1] = acc[3] + b1;
        }
        __syncthreads();
    }
}

// ---------------- launch ------------------------------------------------------
extern "C" void kernel_launch(void* const* d_in, const int* in_sizes, int n_in,
                              void* d_out, int out_size) {
    (void)in_sizes; (void)n_in; (void)out_size;
    const float* xd  = (const float*)d_in[0];
    const float* xm  = (const float*)d_in[1];
    const float* xt  = (const float*)d_in[2];
    const int*   xti = (const int*)d_in[3];
    const int*   yti = (const int*)d_in[4];

    const float* ug_w1 = (const float*)d_in[5];
    const float* ug_b1 = (const float*)d_in[6];
    const float* ug_w2 = (const float*)d_in[7];
    const float* ug_b2 = (const float*)d_in[8];
    const float* rg_w1 = (const float*)d_in[9];
    const float* rg_b1 = (const float*)d_in[10];
    const float* rg_w2 = (const float*)d_in[11];
    const float* rg_b2 = (const float*)d_in[12];
    const float* ns_w1 = (const float*)d_in[13];
    const float* ns_b1 = (const float*)d_in[14];
    const float* ns_w2 = (const float*)d_in[15];
    const float* ns_b2 = (const float*)d_in[16];
    const float* out_w1 = (const float*)d_in[17];
    const float* out_b1 = (const float*)d_in[18];
    const float* out_w2 = (const float*)d_in[19];
    const float* out_b2 = (const float*)d_in[20];
    const float* f_w1  = (const float*)d_in[21];
    const float* f_b1  = (const float*)d_in[22];
    const float* f_w2  = (const float*)d_in[23];
    const float* f_b2  = (const float*)d_in[24];

    cudaFuncSetAttribute(recur_kernel,
                         cudaFuncAttributeMaxDynamicSharedMemorySize, SMEM_BYTES);

    init_kernel<<<1, 256>>>(xt, xti, yti);
    conv_kernel<<<256, 256>>>(f_w1, f_w2, ug_w1, ug_w2, rg_w1, rg_w2,
                              ns_w1, ns_w2, out_w1, out_w2);

    recur_kernel<<<GRID, NTHR, SMEM_BYTES>>>(
        xd, xm,
        ug_b1, ug_b2, rg_b1, rg_b2, ns_b1, ns_b2,
        out_b1, out_b2, f_b1, f_b2,
        (float*)d_out);
}